// round 11
// baseline (speedup 1.0000x reference)
#include <cuda_runtime.h>
#include <math.h>

#define H_DIM 1024
#define NAG 256
#define BTOK 8192
#define NTH 256
#define SB 32
#define GRID_MAIN 444
#define BUILD_BLOCKS 32
#define LN_EPS 1e-5f
#define ALPHA_MAX 5.0f

// ---- global scratch ----
__device__ int g_cnt[NAG];
__device__ int g_cnt2[NAG];
__device__ int g_toks[NAG][BTOK];
__device__ int g_items[1024];
__device__ int g_nitems;
__device__ int g_ifetch;
__device__ int g_done;

// fused: scatter tokens by agent, then last block builds the work-item list
__global__ void build_all_kernel(const int* __restrict__ ids) {
    __shared__ int s_last;
    int i = blockIdx.x * blockDim.x + threadIdx.x;
    if (i == 0) { g_nitems = 0; g_ifetch = 0; }
    if (i < BTOK) {
        int a = ids[i] & (NAG - 1);
        int p = atomicAdd(&g_cnt[a], 1);
        g_toks[a][p] = i;
    }
    __threadfence();
    if (threadIdx.x == 0) {
        int d = atomicAdd(&g_done, 1);
        s_last = (d == BUILD_BLOCKS - 1) ? 1 : 0;
    }
    __syncthreads();
    if (s_last) {
        int a = threadIdx.x;                 // 256 threads = 256 agents
        int n = g_cnt[a];
        g_cnt[a] = 0;                        // reset for next replay
        g_cnt2[a] = n;
        for (int b = 0; b * SB < n; ++b) {
            int p = atomicAdd(&g_nitems, 1);
            g_items[p] = a | (b << 8);
        }
        if (a == 0) g_done = 0;
    }
}

// ---- cp.async helpers ----
__device__ __forceinline__ void cp16(void* s, const void* g) {
    unsigned sa = (unsigned)__cvta_generic_to_shared(s);
    asm volatile("cp.async.cg.shared.global [%0], [%1], 16;\n" :: "r"(sa), "l"(g));
}
#define CP_COMMIT() asm volatile("cp.async.commit_group;\n" ::: "memory")
#define CP_WAIT1()  asm volatile("cp.async.wait_group 1;\n" ::: "memory")
#define CP_WAIT0()  asm volatile("cp.async.wait_group 0;\n" ::: "memory")

// SMEM: ubuf 2x4096 @0, hbuf 2x4096 @8192, stoks @16384
#define OFF_HB 8192
#define OFF_TK 16384
#define SMEM_BYTES ((16384 + 32) * 4)

__global__ __launch_bounds__(NTH, 3)
void div_inject_kernel(const float* __restrict__ h,
                       const float* __restrict__ log_alpha,
                       const float* __restrict__ gamma,
                       const float* __restrict__ beta,
                       const float* __restrict__ pu,
                       const float* __restrict__ pv,
                       float*       __restrict__ out)
{
    extern __shared__ float smem[];
    float* ubuf  = smem;
    float* hbuf  = smem + OFF_HB;
    int*   stoks = (int*)(smem + OFF_TK);
    __shared__ int s_item;

    const int tid  = threadIdx.x;
    const int lane = tid & 31;
    const int wid  = tid >> 5;

    const float alpha = fminf(expf(log_alpha[0]), ALPHA_MAX);
    const float4* h4  = (const float4*)h;
    float4* out4 = (float4*)out;
    const int nitems = g_nitems;

    for (;;) {
        if (tid == 0) s_item = atomicAdd(&g_ifetch, 1);
        __syncthreads();
        const int it = s_item;
        if (it >= nitems) break;

        const int info  = g_items[it];
        const int agent = info & 255;
        const int base  = (info >> 8) * SB;
        const int nb    = min(SB, g_cnt2[agent] - base);
        const int* toks = g_toks[agent];
        const float4* pu4 = (const float4*)pu + (size_t)agent * 8192;
        const float4* pv4 = (const float4*)pv + (size_t)agent * 8192;

        if (tid < SB) stoks[tid] = toks[base + min(tid, nb - 1)];
        __syncthreads();

        const bool gvalid = (4 * wid) < nb;
        int  gt[4]; bool vd[4]; int tk[4];
        #pragma unroll
        for (int i = 0; i < 4; ++i) {
            tk[i] = min(4 * wid + i, nb - 1);
            vd[i] = (4 * wid + i) < nb;
            gt[i] = stoks[tk[i]];
        }

        // ---- stage group 0: U chunk0 + h chunk0 ----
        {
            float4* du = (float4*)ubuf;
            float4* dh = (float4*)hbuf;
            #pragma unroll
            for (int i = 0; i < 4; ++i) {
                const int idx = tid + i * 256;
                cp16(du + idx, pu4 + idx);
                const int tok = idx >> 5, cc = idx & 31;
                cp16(dh + idx, h4 + (size_t)stoks[tok] * 256 + cc);
            }
            CP_COMMIT();
        }

        // ================= phase A =================
        float4 a0 = make_float4(0.f,0.f,0.f,0.f);
        float4 a1 = make_float4(0.f,0.f,0.f,0.f);
        float4 a2 = make_float4(0.f,0.f,0.f,0.f);
        float4 a3 = make_float4(0.f,0.f,0.f,0.f);

        #pragma unroll 1
        for (int c = 0; c < 8; ++c) {
            const int nxt = (c + 1) & 1;
            if (c < 7) {
                float4* du = (float4*)(ubuf + nxt * 4096);
                float4* dh = (float4*)(hbuf + nxt * 4096);
                #pragma unroll
                for (int i = 0; i < 4; ++i) {
                    const int idx = tid + i * 256;
                    cp16(du + idx, pu4 + (c + 1) * 1024 + idx);
                    const int tok = idx >> 5, cc = idx & 31;
                    cp16(dh + idx, h4 + (size_t)stoks[tok] * 256 + (c + 1) * 32 + cc);
                }
            } else {
                float4* dv = (float4*)(ubuf + nxt * 4096);
                #pragma unroll
                for (int i = 0; i < 4; ++i) {
                    const int idx = tid + i * 256;
                    const int r = idx >> 5, cc = idx & 31;
                    cp16(dv + idx, pv4 + r * 256 + cc);
                }
            }
            CP_COMMIT();
            CP_WAIT1();
            __syncthreads();

            if (gvalid) {
                const float*  ubl = ubuf + (c & 1) * 4096 + lane;
                const float4* hb = (const float4*)(hbuf + (c & 1) * 4096);
                const float4* hp0 = hb + tk[0] * 32;
                const float4* hp1 = hb + tk[1] * 32;
                const float4* hp2 = hb + tk[2] * 32;
                const float4* hp3 = hb + tk[3] * 32;

                #pragma unroll 4
                for (int k4 = 0; k4 < 32; ++k4) {
                    float4 x0 = hp0[k4];
                    float4 x1 = hp1[k4];
                    float4 x2 = hp2[k4];
                    float4 x3 = hp3[k4];
                    const float* up = ubl + k4 * 128;
                    float u0 = up[0];
                    float u1 = up[32];
                    float u2 = up[64];
                    float u3 = up[96];
                    a0.x = fmaf(x0.x,u0,a0.x); a0.y = fmaf(x0.y,u1,a0.y);
                    a0.z = fmaf(x0.z,u2,a0.z); a0.w = fmaf(x0.w,u3,a0.w);
                    a1.x = fmaf(x1.x,u0,a1.x); a1.y = fmaf(x1.y,u1,a1.y);
                    a1.z = fmaf(x1.z,u2,a1.z); a1.w = fmaf(x1.w,u3,a1.w);
                    a2.x = fmaf(x2.x,u0,a2.x); a2.y = fmaf(x2.y,u1,a2.y);
                    a2.z = fmaf(x2.z,u2,a2.z); a2.w = fmaf(x2.w,u3,a2.w);
                    a3.x = fmaf(x3.x,u0,a3.x); a3.y = fmaf(x3.y,u1,a3.y);
                    a3.z = fmaf(x3.z,u2,a3.z); a3.w = fmaf(x3.w,u3,a3.w);
                }
            }
            __syncthreads();
        }
        const float iv0 = (a0.x + a0.y) + (a0.z + a0.w);
        const float iv1 = (a1.x + a1.y) + (a1.z + a1.w);
        const float iv2 = (a2.x + a2.y) + (a2.z + a2.w);
        const float iv3 = (a3.x + a3.y) + (a3.z + a3.w);

        // ================= phase B =================
        float s0=0.f, s1=0.f, s2=0.f, s3=0.f;
        float q0=0.f, q1=0.f, q2=0.f, q3=0.f;

        #pragma unroll 1
        for (int c = 0; c < 8; ++c) {
            if (c < 7) {
                float4* dv = (float4*)(ubuf + ((c + 1) & 1) * 4096);
                #pragma unroll
                for (int i = 0; i < 4; ++i) {
                    const int idx = tid + i * 256;
                    const int r = idx >> 5, cc = idx & 31;
                    cp16(dv + idx, pv4 + r * 256 + (c + 1) * 32 + cc);
                }
                CP_COMMIT();
                CP_WAIT1();
            } else {
                CP_WAIT0();
            }
            __syncthreads();

            if (gvalid) {
                const float4* vb = (const float4*)(ubuf + (c & 1) * 4096);

                float4 p0 = make_float4(0.f,0.f,0.f,0.f);
                float4 p1 = make_float4(0.f,0.f,0.f,0.f);
                float4 p2 = make_float4(0.f,0.f,0.f,0.f);
                float4 p3 = make_float4(0.f,0.f,0.f,0.f);

                #pragma unroll 4
                for (int r = 0; r < 32; ++r) {
                    const float b0 = __shfl_sync(0xffffffffu, iv0, r);
                    const float b1 = __shfl_sync(0xffffffffu, iv1, r);
                    const float b2 = __shfl_sync(0xffffffffu, iv2, r);
                    const float b3 = __shfl_sync(0xffffffffu, iv3, r);
                    float4 v = vb[r * 32 + lane];
                    p0.x = fmaf(b0,v.x,p0.x); p0.y = fmaf(b0,v.y,p0.y);
                    p0.z = fmaf(b0,v.z,p0.z); p0.w = fmaf(b0,v.w,p0.w);
                    p1.x = fmaf(b1,v.x,p1.x); p1.y = fmaf(b1,v.y,p1.y);
                    p1.z = fmaf(b1,v.z,p1.z); p1.w = fmaf(b1,v.w,p1.w);
                    p2.x = fmaf(b2,v.x,p2.x); p2.y = fmaf(b2,v.y,p2.y);
                    p2.z = fmaf(b2,v.z,p2.z); p2.w = fmaf(b2,v.w,p2.w);
                    p3.x = fmaf(b3,v.x,p3.x); p3.y = fmaf(b3,v.y,p3.y);
                    p3.z = fmaf(b3,v.z,p3.z); p3.w = fmaf(b3,v.w,p3.w);
                }

                if (vd[0]) {
                    float4 hv = h4[(size_t)gt[0] * 256 + c * 32 + lane];
                    float4 d;
                    d.x = fmaf(alpha,p0.x,hv.x); d.y = fmaf(alpha,p0.y,hv.y);
                    d.z = fmaf(alpha,p0.z,hv.z); d.w = fmaf(alpha,p0.w,hv.w);
                    s0 += (d.x + d.y) + (d.z + d.w);
                    q0 += d.x*d.x + d.y*d.y + d.z*d.z + d.w*d.w;
                    out4[(size_t)gt[0] * 256 + c * 32 + lane] = d;
                }
                if (vd[1]) {
                    float4 hv = h4[(size_t)gt[1] * 256 + c * 32 + lane];
                    float4 d;
                    d.x = fmaf(alpha,p1.x,hv.x); d.y = fmaf(alpha,p1.y,hv.y);
                    d.z = fmaf(alpha,p1.z,hv.z); d.w = fmaf(alpha,p1.w,hv.w);
                    s1 += (d.x + d.y) + (d.z + d.w);
                    q1 += d.x*d.x + d.y*d.y + d.z*d.z + d.w*d.w;
                    out4[(size_t)gt[1] * 256 + c * 32 + lane] = d;
                }
                if (vd[2]) {
                    float4 hv = h4[(size_t)gt[2] * 256 + c * 32 + lane];
                    float4 d;
                    d.x = fmaf(alpha,p2.x,hv.x); d.y = fmaf(alpha,p2.y,hv.y);
                    d.z = fmaf(alpha,p2.z,hv.z); d.w = fmaf(alpha,p2.w,hv.w);
                    s2 += (d.x + d.y) + (d.z + d.w);
                    q2 += d.x*d.x + d.y*d.y + d.z*d.z + d.w*d.w;
                    out4[(size_t)gt[2] * 256 + c * 32 + lane] = d;
                }
                if (vd[3]) {
                    float4 hv = h4[(size_t)gt[3] * 256 + c * 32 + lane];
                    float4 d;
                    d.x = fmaf(alpha,p3.x,hv.x); d.y = fmaf(alpha,p3.y,hv.y);
                    d.z = fmaf(alpha,p3.z,hv.z); d.w = fmaf(alpha,p3.w,hv.w);
                    s3 += (d.x + d.y) + (d.z + d.w);
                    q3 += d.x*d.x + d.y*d.y + d.z*d.z + d.w*d.w;
                    out4[(size_t)gt[3] * 256 + c * 32 + lane] = d;
                }
            }
            __syncthreads();
        }

        // ---- LN finalize + normalize (valid groups only) ----
        if (gvalid) {
            #pragma unroll
            for (int o = 16; o > 0; o >>= 1) {
                s0 += __shfl_xor_sync(0xffffffffu, s0, o);
                q0 += __shfl_xor_sync(0xffffffffu, q0, o);
                s1 += __shfl_xor_sync(0xffffffffu, s1, o);
                q1 += __shfl_xor_sync(0xffffffffu, q1, o);
                s2 += __shfl_xor_sync(0xffffffffu, s2, o);
                q2 += __shfl_xor_sync(0xffffffffu, q2, o);
                s3 += __shfl_xor_sync(0xffffffffu, s3, o);
                q3 += __shfl_xor_sync(0xffffffffu, q3, o);
            }
            float mean[4], rstd[4];
            mean[0] = s0 * (1.0f/H_DIM);
            mean[1] = s1 * (1.0f/H_DIM);
            mean[2] = s2 * (1.0f/H_DIM);
            mean[3] = s3 * (1.0f/H_DIM);
            rstd[0] = rsqrtf(q0*(1.0f/H_DIM) - mean[0]*mean[0] + LN_EPS);
            rstd[1] = rsqrtf(q1*(1.0f/H_DIM) - mean[1]*mean[1] + LN_EPS);
            rstd[2] = rsqrtf(q2*(1.0f/H_DIM) - mean[2]*mean[2] + LN_EPS);
            rstd[3] = rsqrtf(q3*(1.0f/H_DIM) - mean[3]*mean[3] + LN_EPS);

            const float4* g4 = (const float4*)gamma;
            const float4* b4 = (const float4*)beta;
            #pragma unroll
            for (int i = 0; i < 4; ++i) {
                if (!vd[i]) continue;
                const float mn = mean[i], rs = rstd[i];
                float4* op = out4 + (size_t)gt[i] * 256 + lane;
                #pragma unroll
                for (int c = 0; c < 8; ++c) {
                    float4 d = op[c * 32];
                    float4 g = g4[c * 32 + lane];
                    float4 bb = b4[c * 32 + lane];
                    float4 o_;
                    o_.x = (d.x - mn) * rs * g.x + bb.x;
                    o_.y = (d.y - mn) * rs * g.y + bb.y;
                    o_.z = (d.z - mn) * rs * g.z + bb.z;
                    o_.w = (d.w - mn) * rs * g.w + bb.w;
                    op[c * 32] = o_;
                }
            }
        }
        __syncthreads();
    }
}

extern "C" void kernel_launch(void* const* d_in, const int* in_sizes, int n_in,
                              void* d_out, int out_size)
{
    const float* h     = (const float*)d_in[0];
    const float* la    = (const float*)d_in[1];
    const float* gamma = (const float*)d_in[2];
    const float* beta  = (const float*)d_in[3];
    const float* pu    = (const float*)d_in[4];
    const float* pv    = (const float*)d_in[5];
    const int*   ids   = (const int*)d_in[6];
    float*       out   = (float*)d_out;

    build_all_kernel<<<BUILD_BLOCKS, NTH>>>(ids);

    cudaFuncSetAttribute(div_inject_kernel,
                         cudaFuncAttributeMaxDynamicSharedMemorySize, SMEM_BYTES);
    div_inject_kernel<<<GRID_MAIN, NTH, SMEM_BYTES>>>(h, la, gamma, beta, pu, pv, out);
}

// round 12
// speedup vs baseline: 1.0342x; 1.0342x over previous
#include <cuda_runtime.h>
#include <math.h>

#define H_DIM 1024
#define NAG 256
#define BTOK 8192
#define NTH 256
#define SB 32
#define GRID_MAIN 296
#define BUILD_BLOCKS 32
#define LN_EPS 1e-5f
#define ALPHA_MAX 5.0f

typedef unsigned long long u64;

// ---- global scratch ----
__device__ int g_cnt[NAG];
__device__ int g_cnt2[NAG];
__device__ int g_toks[NAG][BTOK];
__device__ int g_items[1024];
__device__ int g_nitems;
__device__ int g_ifetch;
__device__ int g_done;

// fused prepass: scatter tokens by agent; last block builds work-item list
__global__ void build_all_kernel(const int* __restrict__ ids) {
    __shared__ int s_last;
    int i = blockIdx.x * blockDim.x + threadIdx.x;
    if (i == 0) { g_nitems = 0; g_ifetch = 0; }
    if (i < BTOK) {
        int a = ids[i] & (NAG - 1);
        int p = atomicAdd(&g_cnt[a], 1);
        g_toks[a][p] = i;
    }
    __threadfence();
    if (threadIdx.x == 0) {
        int d = atomicAdd(&g_done, 1);
        s_last = (d == BUILD_BLOCKS - 1) ? 1 : 0;
    }
    __syncthreads();
    if (s_last) {
        int a = threadIdx.x;
        int n = g_cnt[a];
        g_cnt[a] = 0;
        g_cnt2[a] = n;
        for (int b = 0; b * SB < n; ++b) {
            int p = atomicAdd(&g_nitems, 1);
            g_items[p] = a | (b << 8);
        }
        if (a == 0) g_done = 0;
    }
}

// ---- f32x2 packed math ----
__device__ __forceinline__ u64 fma2(u64 a, u64 b, u64 c) {
    u64 d;
    asm("fma.rn.f32x2 %0, %1, %2, %3;" : "=l"(d) : "l"(a), "l"(b), "l"(c));
    return d;
}
__device__ __forceinline__ u64 add2(u64 a, u64 b) {
    u64 d;
    asm("add.rn.f32x2 %0, %1, %2;" : "=l"(d) : "l"(a), "l"(b));
    return d;
}
__device__ __forceinline__ u64 mul2(u64 a, u64 b) {
    u64 d;
    asm("mul.rn.f32x2 %0, %1, %2;" : "=l"(d) : "l"(a), "l"(b));
    return d;
}
__device__ __forceinline__ u64 pack2(float lo, float hi) {
    u64 d;
    asm("mov.b64 %0, {%1, %2};" : "=l"(d) : "f"(lo), "f"(hi));
    return d;
}
__device__ __forceinline__ void unpack2(u64 v, float& lo, float& hi) {
    asm("mov.b64 {%0, %1}, %2;" : "=f"(lo), "=f"(hi) : "l"(v));
}

// ---- cp.async helpers ----
__device__ __forceinline__ void cp16(void* s, const void* g) {
    unsigned sa = (unsigned)__cvta_generic_to_shared(s);
    asm volatile("cp.async.cg.shared.global [%0], [%1], 16;\n" :: "r"(sa), "l"(g));
}
#define CP_COMMIT() asm volatile("cp.async.commit_group;\n" ::: "memory")
#define CP_WAIT1()  asm volatile("cp.async.wait_group 1;\n" ::: "memory")
#define CP_WAIT0()  asm volatile("cp.async.wait_group 0;\n" ::: "memory")

// SMEM: ubuf 2x4096 @0, hbuf 2x4096 @8192, stoks @16384
#define OFF_HB 8192
#define OFF_TK 16384
#define SMEM_BYTES ((16384 + 32) * 4)

__global__ __launch_bounds__(NTH, 2)
void div_inject_kernel(const float* __restrict__ h,
                       const float* __restrict__ log_alpha,
                       const float* __restrict__ gamma,
                       const float* __restrict__ beta,
                       const float* __restrict__ pu,
                       const float* __restrict__ pv,
                       float*       __restrict__ out)
{
    extern __shared__ float smem[];
    float* ubuf  = smem;
    float* hbuf  = smem + OFF_HB;
    int*   stoks = (int*)(smem + OFF_TK);
    __shared__ int s_item;

    const int tid  = threadIdx.x;
    const int lane = tid & 31;
    const int wid  = tid >> 5;

    const float alpha = fminf(expf(log_alpha[0]), ALPHA_MAX);
    const u64 al2 = pack2(alpha, alpha);
    const float4* h4  = (const float4*)h;
    float4* out4 = (float4*)out;
    const int nitems = g_nitems;

    for (;;) {
        if (tid == 0) s_item = atomicAdd(&g_ifetch, 1);
        __syncthreads();
        const int it = s_item;
        if (it >= nitems) break;

        const int info  = g_items[it];
        const int agent = info & 255;
        const int base  = (info >> 8) * SB;
        const int nb    = min(SB, g_cnt2[agent] - base);
        const int* toks = g_toks[agent];
        const float4* pu4 = (const float4*)pu + (size_t)agent * 8192;
        const float4* pv4 = (const float4*)pv + (size_t)agent * 8192;

        if (tid < SB) stoks[tid] = toks[base + min(tid, nb - 1)];
        __syncthreads();

        const bool gvalid = (4 * wid) < nb;
        int  gt[4]; bool vd[4]; int tk[4];
        #pragma unroll
        for (int i = 0; i < 4; ++i) {
            tk[i] = min(4 * wid + i, nb - 1);
            vd[i] = (4 * wid + i) < nb;
            gt[i] = stoks[tk[i]];
        }

        // ---- stage group 0: U chunk0 + h chunk0 ----
        {
            float4* du = (float4*)ubuf;
            float4* dh = (float4*)hbuf;
            #pragma unroll
            for (int i = 0; i < 4; ++i) {
                const int idx = tid + i * 256;
                cp16(du + idx, pu4 + idx);
                const int tok = idx >> 5, cc = idx & 31;
                cp16(dh + idx, h4 + (size_t)stoks[tok] * 256 + cc);
            }
            CP_COMMIT();
        }

        // ================= phase A (f32x2) =================
        u64 A0x = 0, A0z = 0, A1x = 0, A1z = 0;
        u64 A2x = 0, A2z = 0, A3x = 0, A3z = 0;

        #pragma unroll 1
        for (int c = 0; c < 8; ++c) {
            const int nxt = (c + 1) & 1;
            if (c < 7) {
                float4* du = (float4*)(ubuf + nxt * 4096);
                float4* dh = (float4*)(hbuf + nxt * 4096);
                #pragma unroll
                for (int i = 0; i < 4; ++i) {
                    const int idx = tid + i * 256;
                    cp16(du + idx, pu4 + (c + 1) * 1024 + idx);
                    const int tok = idx >> 5, cc = idx & 31;
                    cp16(dh + idx, h4 + (size_t)stoks[tok] * 256 + (c + 1) * 32 + cc);
                }
            } else {
                float4* dv = (float4*)(ubuf + nxt * 4096);
                #pragma unroll
                for (int i = 0; i < 4; ++i) {
                    const int idx = tid + i * 256;
                    const int r = idx >> 5, cc = idx & 31;
                    cp16(dv + idx, pv4 + r * 256 + cc);
                }
            }
            CP_COMMIT();
            CP_WAIT1();
            __syncthreads();

            if (gvalid) {
                const float* ubl = ubuf + (c & 1) * 4096 + lane;
                const float* hbc = hbuf + (c & 1) * 4096;
                const ulonglong2* hp0 = (const ulonglong2*)hbc + tk[0] * 32;
                const ulonglong2* hp1 = (const ulonglong2*)hbc + tk[1] * 32;
                const ulonglong2* hp2 = (const ulonglong2*)hbc + tk[2] * 32;
                const ulonglong2* hp3 = (const ulonglong2*)hbc + tk[3] * 32;

                #pragma unroll 4
                for (int k4 = 0; k4 < 32; ++k4) {
                    ulonglong2 x0 = hp0[k4];
                    ulonglong2 x1 = hp1[k4];
                    ulonglong2 x2 = hp2[k4];
                    ulonglong2 x3 = hp3[k4];
                    const float* up = ubl + k4 * 128;
                    u64 u01 = pack2(up[0],  up[32]);
                    u64 u23 = pack2(up[64], up[96]);
                    A0x = fma2(x0.x, u01, A0x); A0z = fma2(x0.y, u23, A0z);
                    A1x = fma2(x1.x, u01, A1x); A1z = fma2(x1.y, u23, A1z);
                    A2x = fma2(x2.x, u01, A2x); A2z = fma2(x2.y, u23, A2z);
                    A3x = fma2(x3.x, u01, A3x); A3z = fma2(x3.y, u23, A3z);
                }
            }
            __syncthreads();
        }
        float iv0, iv1, iv2, iv3;
        {
            float f0, f1, f2, f3;
            unpack2(A0x, f0, f1); unpack2(A0z, f2, f3); iv0 = (f0 + f1) + (f2 + f3);
            unpack2(A1x, f0, f1); unpack2(A1z, f2, f3); iv1 = (f0 + f1) + (f2 + f3);
            unpack2(A2x, f0, f1); unpack2(A2z, f2, f3); iv2 = (f0 + f1) + (f2 + f3);
            unpack2(A3x, f0, f1); unpack2(A3z, f2, f3); iv3 = (f0 + f1) + (f2 + f3);
        }

        // ================= phase B (f32x2) =================
        u64 S0 = 0, S1 = 0, S2 = 0, S3 = 0;
        u64 Q0 = 0, Q1 = 0, Q2 = 0, Q3 = 0;

        #pragma unroll 1
        for (int c = 0; c < 8; ++c) {
            if (c < 7) {
                float4* dv = (float4*)(ubuf + ((c + 1) & 1) * 4096);
                #pragma unroll
                for (int i = 0; i < 4; ++i) {
                    const int idx = tid + i * 256;
                    const int r = idx >> 5, cc = idx & 31;
                    cp16(dv + idx, pv4 + r * 256 + (c + 1) * 32 + cc);
                }
                CP_COMMIT();
                CP_WAIT1();
            } else {
                CP_WAIT0();
            }
            __syncthreads();

            if (gvalid) {
                const ulonglong2* vb = (const ulonglong2*)(ubuf + (c & 1) * 4096);

                u64 P0x = 0, P0z = 0, P1x = 0, P1z = 0;
                u64 P2x = 0, P2z = 0, P3x = 0, P3z = 0;

                #pragma unroll 4
                for (int r = 0; r < 32; ++r) {
                    const float b0 = __shfl_sync(0xffffffffu, iv0, r);
                    const float b1 = __shfl_sync(0xffffffffu, iv1, r);
                    const float b2 = __shfl_sync(0xffffffffu, iv2, r);
                    const float b3 = __shfl_sync(0xffffffffu, iv3, r);
                    ulonglong2 v = vb[r * 32 + lane];
                    u64 bb0 = pack2(b0, b0);
                    u64 bb1 = pack2(b1, b1);
                    u64 bb2 = pack2(b2, b2);
                    u64 bb3 = pack2(b3, b3);
                    P0x = fma2(bb0, v.x, P0x); P0z = fma2(bb0, v.y, P0z);
                    P1x = fma2(bb1, v.x, P1x); P1z = fma2(bb1, v.y, P1z);
                    P2x = fma2(bb2, v.x, P2x); P2z = fma2(bb2, v.y, P2z);
                    P3x = fma2(bb3, v.x, P3x); P3z = fma2(bb3, v.y, P3z);
                }

                // residual d = h + alpha*p, unnormalized store, f32x2 sums
                if (vd[0]) {
                    ulonglong2 hv = *((const ulonglong2*)(h4 + (size_t)gt[0] * 256) + c * 32 + lane);
                    u64 dx = fma2(al2, P0x, hv.x);
                    u64 dz = fma2(al2, P0z, hv.y);
                    S0 = add2(S0, add2(dx, dz));
                    Q0 = fma2(dx, dx, Q0); Q0 = fma2(dz, dz, Q0);
                    ulonglong2 dd; dd.x = dx; dd.y = dz;
                    *((ulonglong2*)(out4 + (size_t)gt[0] * 256) + c * 32 + lane) = dd;
                }
                if (vd[1]) {
                    ulonglong2 hv = *((const ulonglong2*)(h4 + (size_t)gt[1] * 256) + c * 32 + lane);
                    u64 dx = fma2(al2, P1x, hv.x);
                    u64 dz = fma2(al2, P1z, hv.y);
                    S1 = add2(S1, add2(dx, dz));
                    Q1 = fma2(dx, dx, Q1); Q1 = fma2(dz, dz, Q1);
                    ulonglong2 dd; dd.x = dx; dd.y = dz;
                    *((ulonglong2*)(out4 + (size_t)gt[1] * 256) + c * 32 + lane) = dd;
                }
                if (vd[2]) {
                    ulonglong2 hv = *((const ulonglong2*)(h4 + (size_t)gt[2] * 256) + c * 32 + lane);
                    u64 dx = fma2(al2, P2x, hv.x);
                    u64 dz = fma2(al2, P2z, hv.y);
                    S2 = add2(S2, add2(dx, dz));
                    Q2 = fma2(dx, dx, Q2); Q2 = fma2(dz, dz, Q2);
                    ulonglong2 dd; dd.x = dx; dd.y = dz;
                    *((ulonglong2*)(out4 + (size_t)gt[2] * 256) + c * 32 + lane) = dd;
                }
                if (vd[3]) {
                    ulonglong2 hv = *((const ulonglong2*)(h4 + (size_t)gt[3] * 256) + c * 32 + lane);
                    u64 dx = fma2(al2, P3x, hv.x);
                    u64 dz = fma2(al2, P3z, hv.y);
                    S3 = add2(S3, add2(dx, dz));
                    Q3 = fma2(dx, dx, Q3); Q3 = fma2(dz, dz, Q3);
                    ulonglong2 dd; dd.x = dx; dd.y = dz;
                    *((ulonglong2*)(out4 + (size_t)gt[3] * 256) + c * 32 + lane) = dd;
                }
            }
            __syncthreads();
        }

        // ---- LN finalize + normalize (valid groups only) ----
        if (gvalid) {
            float s0, s1, s2, s3, q0, q1, q2, q3;
            {
                float lo, hi;
                unpack2(S0, lo, hi); s0 = lo + hi;
                unpack2(S1, lo, hi); s1 = lo + hi;
                unpack2(S2, lo, hi); s2 = lo + hi;
                unpack2(S3, lo, hi); s3 = lo + hi;
                unpack2(Q0, lo, hi); q0 = lo + hi;
                unpack2(Q1, lo, hi); q1 = lo + hi;
                unpack2(Q2, lo, hi); q2 = lo + hi;
                unpack2(Q3, lo, hi); q3 = lo + hi;
            }
            #pragma unroll
            for (int o = 16; o > 0; o >>= 1) {
                s0 += __shfl_xor_sync(0xffffffffu, s0, o);
                q0 += __shfl_xor_sync(0xffffffffu, q0, o);
                s1 += __shfl_xor_sync(0xffffffffu, s1, o);
                q1 += __shfl_xor_sync(0xffffffffu, q1, o);
                s2 += __shfl_xor_sync(0xffffffffu, s2, o);
                q2 += __shfl_xor_sync(0xffffffffu, q2, o);
                s3 += __shfl_xor_sync(0xffffffffu, s3, o);
                q3 += __shfl_xor_sync(0xffffffffu, q3, o);
            }
            float mean[4], rstd[4];
            mean[0] = s0 * (1.0f/H_DIM);
            mean[1] = s1 * (1.0f/H_DIM);
            mean[2] = s2 * (1.0f/H_DIM);
            mean[3] = s3 * (1.0f/H_DIM);
            rstd[0] = rsqrtf(q0*(1.0f/H_DIM) - mean[0]*mean[0] + LN_EPS);
            rstd[1] = rsqrtf(q1*(1.0f/H_DIM) - mean[1]*mean[1] + LN_EPS);
            rstd[2] = rsqrtf(q2*(1.0f/H_DIM) - mean[2]*mean[2] + LN_EPS);
            rstd[3] = rsqrtf(q3*(1.0f/H_DIM) - mean[3]*mean[3] + LN_EPS);

            const ulonglong2* g2 = (const ulonglong2*)gamma;
            const ulonglong2* b2 = (const ulonglong2*)beta;
            #pragma unroll
            for (int i = 0; i < 4; ++i) {
                if (!vd[i]) continue;
                const u64 nm2 = pack2(-mean[i], -mean[i]);
                const u64 rs2 = pack2(rstd[i], rstd[i]);
                ulonglong2* op = (ulonglong2*)(out4 + (size_t)gt[i] * 256) + lane;
                #pragma unroll
                for (int c = 0; c < 8; ++c) {
                    ulonglong2 d = op[c * 32];
                    ulonglong2 g = g2[c * 32 + lane];
                    ulonglong2 bb = b2[c * 32 + lane];
                    u64 tx = mul2(add2(d.x, nm2), rs2);
                    u64 tz = mul2(add2(d.y, nm2), rs2);
                    ulonglong2 o_;
                    o_.x = fma2(tx, g.x, bb.x);
                    o_.y = fma2(tz, g.y, bb.y);
                    op[c * 32] = o_;
                }
            }
        }
        __syncthreads();
    }
}

extern "C" void kernel_launch(void* const* d_in, const int* in_sizes, int n_in,
                              void* d_out, int out_size)
{
    const float* h     = (const float*)d_in[0];
    const float* la    = (const float*)d_in[1];
    const float* gamma = (const float*)d_in[2];
    const float* beta  = (const float*)d_in[3];
    const float* pu    = (const float*)d_in[4];
    const float* pv    = (const float*)d_in[5];
    const int*   ids   = (const int*)d_in[6];
    float*       out   = (float*)d_out;

    build_all_kernel<<<BUILD_BLOCKS, NTH>>>(ids);

    cudaFuncSetAttribute(div_inject_kernel,
                         cudaFuncAttributeMaxDynamicSharedMemorySize, SMEM_BYTES);
    div_inject_kernel<<<GRID_MAIN, NTH, SMEM_BYTES>>>(h, la, gamma, beta, pu, pv, out);
}

// round 13
// speedup vs baseline: 1.1549x; 1.1167x over previous
#include <cuda_runtime.h>
#include <math.h>

#define H_DIM 1024
#define NAG 256
#define BTOK 8192
#define NTH 256
#define SB 48
#define TPW 6
#define GRID_MAIN 296
#define BUILD_BLOCKS 32
#define LN_EPS 1e-5f
#define ALPHA_MAX 5.0f

typedef unsigned long long u64;

// ---- global scratch ----
__device__ int g_cnt[NAG];
__device__ int g_cnt2[NAG];
__device__ int g_toks[NAG][BTOK];
__device__ int g_items[1024];
__device__ int g_nitems;
__device__ int g_ifetch;
__device__ int g_done;

__global__ void build_all_kernel(const int* __restrict__ ids) {
    __shared__ int s_last;
    int i = blockIdx.x * blockDim.x + threadIdx.x;
    if (i == 0) { g_nitems = 0; g_ifetch = 0; }
    if (i < BTOK) {
        int a = ids[i] & (NAG - 1);
        int p = atomicAdd(&g_cnt[a], 1);
        g_toks[a][p] = i;
    }
    __threadfence();
    if (threadIdx.x == 0) {
        int d = atomicAdd(&g_done, 1);
        s_last = (d == BUILD_BLOCKS - 1) ? 1 : 0;
    }
    __syncthreads();
    if (s_last) {
        int a = threadIdx.x;
        int n = g_cnt[a];
        g_cnt[a] = 0;
        g_cnt2[a] = n;
        for (int b = 0; b * SB < n; ++b) {
            int p = atomicAdd(&g_nitems, 1);
            g_items[p] = a | (b << 8);
        }
        if (a == 0) g_done = 0;
    }
}

// ---- f32x2 packed math ----
__device__ __forceinline__ u64 fma2(u64 a, u64 b, u64 c) {
    u64 d;
    asm("fma.rn.f32x2 %0, %1, %2, %3;" : "=l"(d) : "l"(a), "l"(b), "l"(c));
    return d;
}
__device__ __forceinline__ u64 add2(u64 a, u64 b) {
    u64 d;
    asm("add.rn.f32x2 %0, %1, %2;" : "=l"(d) : "l"(a), "l"(b));
    return d;
}
__device__ __forceinline__ u64 mul2(u64 a, u64 b) {
    u64 d;
    asm("mul.rn.f32x2 %0, %1, %2;" : "=l"(d) : "l"(a), "l"(b));
    return d;
}
__device__ __forceinline__ u64 pack2(float lo, float hi) {
    u64 d;
    asm("mov.b64 %0, {%1, %2};" : "=l"(d) : "f"(lo), "f"(hi));
    return d;
}
__device__ __forceinline__ void unpack2(u64 v, float& lo, float& hi) {
    asm("mov.b64 {%0, %1}, %2;" : "=f"(lo), "=f"(hi) : "l"(v));
}

// ---- cp.async helpers ----
__device__ __forceinline__ void cp16(void* s, const void* g) {
    unsigned sa = (unsigned)__cvta_generic_to_shared(s);
    asm volatile("cp.async.cg.shared.global [%0], [%1], 16;\n" :: "r"(sa), "l"(g));
}
#define CP_COMMIT() asm volatile("cp.async.commit_group;\n" ::: "memory")
#define CP_WAIT1()  asm volatile("cp.async.wait_group 1;\n" ::: "memory")
#define CP_WAIT0()  asm volatile("cp.async.wait_group 0;\n" ::: "memory")

// SMEM layout (floats):
//   ubuf   2 x 4096  @ 0      (U/V chunk ping-pong, 2x16KB)
//   hbuf   2 x 6144  @ 8192   (48 tokens x 128 cols, ping-pong, 2x24KB)
//   binter 1536 u64  @ 20480  (48 tokens x 32 r, duplicated pairs, 12KB)
//   stoks  48 int    @ 23552
#define OFF_HB 8192
#define OFF_BI 20480
#define OFF_TK 23552
#define SMEM_BYTES ((23552 + 48) * 4)

__global__ __launch_bounds__(NTH, 2)
void div_inject_kernel(const float* __restrict__ h,
                       const float* __restrict__ log_alpha,
                       const float* __restrict__ gamma,
                       const float* __restrict__ beta,
                       const float* __restrict__ pu,
                       const float* __restrict__ pv,
                       float*       __restrict__ out)
{
    extern __shared__ float smem[];
    float* ubuf  = smem;
    float* hbuf  = smem + OFF_HB;
    u64*   bint  = (u64*)(smem + OFF_BI);
    int*   stoks = (int*)(smem + OFF_TK);
    __shared__ int s_item;

    const int tid  = threadIdx.x;
    const int lane = tid & 31;
    const int wid  = tid >> 5;

    const float alpha = fminf(expf(log_alpha[0]), ALPHA_MAX);
    const u64 al2 = pack2(alpha, alpha);
    const float4* h4 = (const float4*)h;
    const ulonglong2* h2 = (const ulonglong2*)h;
    ulonglong2* out2 = (ulonglong2*)out;
    const int nitems = g_nitems;

    for (;;) {
        if (tid == 0) s_item = atomicAdd(&g_ifetch, 1);
        __syncthreads();
        const int it = s_item;
        if (it >= nitems) break;

        const int info  = g_items[it];
        const int agent = info & 255;
        const int base  = (info >> 8) * SB;
        const int nb    = min(SB, g_cnt2[agent] - base);
        const int* toks = g_toks[agent];
        const float4* pu4 = (const float4*)pu + (size_t)agent * 8192;
        const float4* pv4 = (const float4*)pv + (size_t)agent * 8192;

        if (tid < SB) stoks[tid] = toks[base + min(tid, nb - 1)];
        __syncthreads();

        const bool gvalid = (TPW * wid) < nb;
        int  gt[TPW]; bool vd[TPW]; int tk[TPW];
        #pragma unroll
        for (int i = 0; i < TPW; ++i) {
            tk[i] = min(TPW * wid + i, nb - 1);
            vd[i] = (TPW * wid + i) < nb;
            gt[i] = stoks[tk[i]];
        }

        // ---- stage group 0: U chunk0 (1024 f4) + h chunk0 (1536 f4) ----
        {
            float4* du = (float4*)ubuf;
            float4* dh = (float4*)hbuf;
            #pragma unroll
            for (int i = 0; i < 4; ++i)
                cp16(du + tid + i * 256, pu4 + tid + i * 256);
            #pragma unroll
            for (int i = 0; i < 6; ++i) {
                const int idx = tid + i * 256;
                const int tok = idx >> 5, cc = idx & 31;
                cp16(dh + idx, h4 + (size_t)stoks[tok] * 256 + cc);
            }
            CP_COMMIT();
        }

        // ================= phase A =================
        u64 Ax[TPW], Az[TPW];
        #pragma unroll
        for (int i = 0; i < TPW; ++i) { Ax[i] = 0; Az[i] = 0; }

        #pragma unroll 1
        for (int c = 0; c < 8; ++c) {
            const int nxt = (c + 1) & 1;
            if (c < 7) {
                float4* du = (float4*)(ubuf + nxt * 4096);
                float4* dh = (float4*)(hbuf + nxt * 6144);
                #pragma unroll
                for (int i = 0; i < 4; ++i)
                    cp16(du + tid + i * 256, pu4 + (c + 1) * 1024 + tid + i * 256);
                #pragma unroll
                for (int i = 0; i < 6; ++i) {
                    const int idx = tid + i * 256;
                    const int tok = idx >> 5, cc = idx & 31;
                    cp16(dh + idx, h4 + (size_t)stoks[tok] * 256 + (c + 1) * 32 + cc);
                }
            } else {
                // cross-phase prefetch: V chunk 0
                float4* dv = (float4*)(ubuf + nxt * 4096);
                #pragma unroll
                for (int i = 0; i < 4; ++i) {
                    const int idx = tid + i * 256;
                    const int r = idx >> 5, cc = idx & 31;
                    cp16(dv + idx, pv4 + r * 256 + cc);
                }
            }
            CP_COMMIT();
            CP_WAIT1();
            __syncthreads();

            if (gvalid) {
                const float* ubl = ubuf + (c & 1) * 4096 + lane;
                const ulonglong2* hb = (const ulonglong2*)(hbuf + (c & 1) * 6144);

                #pragma unroll 4
                for (int k4 = 0; k4 < 32; ++k4) {
                    const float* up = ubl + k4 * 128;
                    u64 u01 = pack2(up[0],  up[32]);
                    u64 u23 = pack2(up[64], up[96]);
                    #pragma unroll
                    for (int i = 0; i < TPW; ++i) {
                        ulonglong2 x = hb[tk[i] * 32 + k4];
                        Ax[i] = fma2(x.x, u01, Ax[i]);
                        Az[i] = fma2(x.y, u23, Az[i]);
                    }
                }
            }
            __syncthreads();
        }

        // write packed (iv,iv) to binter; per-warp private, no CTA barrier needed
        if (gvalid) {
            #pragma unroll
            for (int i = 0; i < TPW; ++i) {
                float f0, f1, f2, f3;
                unpack2(Ax[i], f0, f1);
                unpack2(Az[i], f2, f3);
                const float iv = (f0 + f1) + (f2 + f3);
                bint[tk[i] * 32 + lane] = pack2(iv, iv);
            }
        }
        __syncwarp();

        // ================= phase B =================
        u64 S[TPW], Q[TPW];
        #pragma unroll
        for (int i = 0; i < TPW; ++i) { S[i] = 0; Q[i] = 0; }

        #pragma unroll 1
        for (int c = 0; c < 8; ++c) {
            if (c < 7) {
                float4* dv = (float4*)(ubuf + ((c + 1) & 1) * 4096);
                #pragma unroll
                for (int i = 0; i < 4; ++i) {
                    const int idx = tid + i * 256;
                    const int r = idx >> 5, cc = idx & 31;
                    cp16(dv + idx, pv4 + r * 256 + (c + 1) * 32 + cc);
                }
                CP_COMMIT();
                CP_WAIT1();
            } else {
                CP_WAIT0();
            }
            __syncthreads();

            if (gvalid) {
                const ulonglong2* vb = (const ulonglong2*)(ubuf + (c & 1) * 4096);

                u64 Px[TPW], Pz[TPW];
                #pragma unroll
                for (int i = 0; i < TPW; ++i) { Px[i] = 0; Pz[i] = 0; }

                #pragma unroll 4
                for (int rb = 0; rb < 16; ++rb) {
                    ulonglong2 v0 = vb[(2 * rb)     * 32 + lane];
                    ulonglong2 v1 = vb[(2 * rb + 1) * 32 + lane];
                    #pragma unroll
                    for (int i = 0; i < TPW; ++i) {
                        // (bb[2rb], bb[2rb+1]) duplicated pairs, one broadcast LDS.128
                        ulonglong2 bb = ((const ulonglong2*)(bint + tk[i] * 32))[rb];
                        Px[i] = fma2(bb.x, v0.x, Px[i]);
                        Pz[i] = fma2(bb.x, v0.y, Pz[i]);
                        Px[i] = fma2(bb.y, v1.x, Px[i]);
                        Pz[i] = fma2(bb.y, v1.y, Pz[i]);
                    }
                }

                #pragma unroll
                for (int i = 0; i < TPW; ++i) {
                    if (!vd[i]) continue;
                    ulonglong2 hv = h2[(size_t)gt[i] * 256 + c * 32 + lane];
                    u64 dx = fma2(al2, Px[i], hv.x);
                    u64 dz = fma2(al2, Pz[i], hv.y);
                    S[i] = add2(S[i], add2(dx, dz));
                    Q[i] = fma2(dx, dx, Q[i]);
                    Q[i] = fma2(dz, dz, Q[i]);
                    ulonglong2 dd; dd.x = dx; dd.y = dz;
                    out2[(size_t)gt[i] * 256 + c * 32 + lane] = dd;
                }
            }
            __syncthreads();
        }

        // ---- LN finalize + normalize ----
        if (gvalid) {
            float s[TPW], q[TPW];
            #pragma unroll
            for (int i = 0; i < TPW; ++i) {
                float lo, hi;
                unpack2(S[i], lo, hi); s[i] = lo + hi;
                unpack2(Q[i], lo, hi); q[i] = lo + hi;
            }
            #pragma unroll
            for (int o = 16; o > 0; o >>= 1) {
                #pragma unroll
                for (int i = 0; i < TPW; ++i) {
                    s[i] += __shfl_xor_sync(0xffffffffu, s[i], o);
                    q[i] += __shfl_xor_sync(0xffffffffu, q[i], o);
                }
            }
            const ulonglong2* g2 = (const ulonglong2*)gamma;
            const ulonglong2* b2 = (const ulonglong2*)beta;
            #pragma unroll
            for (int i = 0; i < TPW; ++i) {
                if (!vd[i]) continue;
                const float mn = s[i] * (1.0f / H_DIM);
                const float rs = rsqrtf(q[i] * (1.0f / H_DIM) - mn * mn + LN_EPS);
                const u64 nm2 = pack2(-mn, -mn);
                const u64 rs2 = pack2(rs, rs);
                ulonglong2* op = out2 + (size_t)gt[i] * 256 + lane;
                #pragma unroll
                for (int c = 0; c < 8; ++c) {
                    ulonglong2 d = op[c * 32];
                    ulonglong2 g = g2[c * 32 + lane];
                    ulonglong2 bb = b2[c * 32 + lane];
                    u64 tx = mul2(add2(d.x, nm2), rs2);
                    u64 tz = mul2(add2(d.y, nm2), rs2);
                    ulonglong2 o_;
                    o_.x = fma2(tx, g.x, bb.x);
                    o_.y = fma2(tz, g.y, bb.y);
                    op[c * 32] = o_;
                }
            }
        }
        __syncthreads();
    }
}

extern "C" void kernel_launch(void* const* d_in, const int* in_sizes, int n_in,
                              void* d_out, int out_size)
{
    const float* h     = (const float*)d_in[0];
    const float* la    = (const float*)d_in[1];
    const float* gamma = (const float*)d_in[2];
    const float* beta  = (const float*)d_in[3];
    const float* pu    = (const float*)d_in[4];
    const float* pv    = (const float*)d_in[5];
    const int*   ids   = (const int*)d_in[6];
    float*       out   = (float*)d_out;

    build_all_kernel<<<BUILD_BLOCKS, NTH>>>(ids);

    cudaFuncSetAttribute(div_inject_kernel,
                         cudaFuncAttributeMaxDynamicSharedMemorySize, SMEM_BYTES);
    div_inject_kernel<<<GRID_MAIN, NTH, SMEM_BYTES>>>(h, la, gamma, beta, pu, pv, out);
}

// round 14
// speedup vs baseline: 1.1614x; 1.0056x over previous
#include <cuda_runtime.h>
#include <math.h>

#define H_DIM 1024
#define NAG 256
#define BTOK 8192
#define NTH 256
#define SB 48
#define TPW 6
#define GRID_MAIN 296
#define BUILD_BLOCKS 32
#define LN_EPS 1e-5f
#define ALPHA_MAX 5.0f

typedef unsigned long long u64;

// ---- global scratch ----
__device__ int g_cnt[NAG];
__device__ int g_cnt2[NAG];
__device__ int g_toks[NAG][BTOK];
__device__ int g_items[1024];
__device__ int g_nitems;
__device__ int g_ifetch;
__device__ int g_done;

__global__ void build_all_kernel(const int* __restrict__ ids) {
    __shared__ int s_last;
    int i = blockIdx.x * blockDim.x + threadIdx.x;
    if (i == 0) { g_nitems = 0; g_ifetch = 0; }
    if (i < BTOK) {
        int a = ids[i] & (NAG - 1);
        int p = atomicAdd(&g_cnt[a], 1);
        g_toks[a][p] = i;
    }
    __threadfence();
    if (threadIdx.x == 0) {
        int d = atomicAdd(&g_done, 1);
        s_last = (d == BUILD_BLOCKS - 1) ? 1 : 0;
    }
    __syncthreads();
    if (s_last) {
        int a = threadIdx.x;
        int n = g_cnt[a];
        g_cnt[a] = 0;
        g_cnt2[a] = n;
        for (int b = 0; b * SB < n; ++b) {
            int p = atomicAdd(&g_nitems, 1);
            g_items[p] = a | (b << 8);
        }
        if (a == 0) g_done = 0;
    }
}

// ---- f32x2 packed math ----
__device__ __forceinline__ u64 fma2(u64 a, u64 b, u64 c) {
    u64 d;
    asm("fma.rn.f32x2 %0, %1, %2, %3;" : "=l"(d) : "l"(a), "l"(b), "l"(c));
    return d;
}
__device__ __forceinline__ u64 add2(u64 a, u64 b) {
    u64 d;
    asm("add.rn.f32x2 %0, %1, %2;" : "=l"(d) : "l"(a), "l"(b));
    return d;
}
__device__ __forceinline__ u64 mul2(u64 a, u64 b) {
    u64 d;
    asm("mul.rn.f32x2 %0, %1, %2;" : "=l"(d) : "l"(a), "l"(b));
    return d;
}
__device__ __forceinline__ u64 pack2(float lo, float hi) {
    u64 d;
    asm("mov.b64 %0, {%1, %2};" : "=l"(d) : "f"(lo), "f"(hi));
    return d;
}
__device__ __forceinline__ void unpack2(u64 v, float& lo, float& hi) {
    asm("mov.b64 {%0, %1}, %2;" : "=f"(lo), "=f"(hi) : "l"(v));
}

// ---- cp.async helpers ----
__device__ __forceinline__ void cp16(void* s, const void* g) {
    unsigned sa = (unsigned)__cvta_generic_to_shared(s);
    asm volatile("cp.async.cg.shared.global [%0], [%1], 16;\n" :: "r"(sa), "l"(g));
}
#define CP_COMMIT() asm volatile("cp.async.commit_group;\n" ::: "memory")
#define CP_WAIT2()  asm volatile("cp.async.wait_group 2;\n" ::: "memory")
#define CP_WAIT1()  asm volatile("cp.async.wait_group 1;\n" ::: "memory")
#define CP_WAIT0()  asm volatile("cp.async.wait_group 0;\n" ::: "memory")

// SMEM layout (floats):
//   ring    4 stages x 5120  @ 0      (80 KB; A-stage: U 2048 + h 3072; B-stage: V 4096)
//   binter  1536 u64 (3072 f) @ 20480 (12 KB)
//   stoks   48 int            @ 23552
#define STAGE_F 5120
#define OFF_BI 20480
#define OFF_TK 23552
#define SMEM_BYTES ((23552 + 48) * 4)

// chunk sequence: t in [0,24). t<16: A chunk (U 64 k-rows + h 64 cols). t>=16: V chunk (128 cols).
__device__ __forceinline__ void issue_chunk(int t, float* smem,
                                            const float4* pu4, const float4* pv4,
                                            const float4* h4, const int* stoks, int tid) {
    float4* dst = (float4*)(smem + (t & 3) * STAGE_F);
    if (t < 16) {
        cp16(dst + tid,       pu4 + t * 512 + tid);
        cp16(dst + 256 + tid, pu4 + t * 512 + 256 + tid);
        #pragma unroll
        for (int i = 0; i < 3; ++i) {
            const int idx = tid + i * 256;
            const int tok = idx >> 4, cc = idx & 15;
            cp16(dst + 512 + idx, h4 + (size_t)stoks[tok] * 256 + t * 16 + cc);
        }
    } else {
        const int j = t - 16;
        #pragma unroll
        for (int i = 0; i < 4; ++i) {
            const int idx = tid + i * 256;
            const int r = idx >> 5, cc = idx & 31;
            cp16(dst + idx, pv4 + r * 256 + j * 32 + cc);
        }
    }
}

__global__ __launch_bounds__(NTH, 2)
void div_inject_kernel(const float* __restrict__ h,
                       const float* __restrict__ log_alpha,
                       const float* __restrict__ gamma,
                       const float* __restrict__ beta,
                       const float* __restrict__ pu,
                       const float* __restrict__ pv,
                       float*       __restrict__ out)
{
    extern __shared__ float smem[];
    u64* bint  = (u64*)(smem + OFF_BI);
    int* stoks = (int*)(smem + OFF_TK);
    __shared__ int s_item;

    const int tid  = threadIdx.x;
    const int lane = tid & 31;
    const int wid  = tid >> 5;

    const float alpha = fminf(expf(log_alpha[0]), ALPHA_MAX);
    const u64 al2 = pack2(alpha, alpha);
    const float4* h4 = (const float4*)h;
    const ulonglong2* h2 = (const ulonglong2*)h;
    ulonglong2* out2 = (ulonglong2*)out;
    const int nitems = g_nitems;

    for (;;) {
        if (tid == 0) s_item = atomicAdd(&g_ifetch, 1);
        __syncthreads();
        const int it = s_item;
        if (it >= nitems) break;

        const int info  = g_items[it];
        const int agent = info & 255;
        const int base  = (info >> 8) * SB;
        const int nb    = min(SB, g_cnt2[agent] - base);
        const int* toks = g_toks[agent];
        const float4* pu4 = (const float4*)pu + (size_t)agent * 8192;
        const float4* pv4 = (const float4*)pv + (size_t)agent * 8192;

        if (tid < SB) stoks[tid] = toks[base + min(tid, nb - 1)];
        __syncthreads();

        const bool gvalid = (TPW * wid) < nb;
        int  gt[TPW]; bool vd[TPW]; int tk[TPW];
        #pragma unroll
        for (int i = 0; i < TPW; ++i) {
            tk[i] = min(TPW * wid + i, nb - 1);
            vd[i] = (TPW * wid + i) < nb;
            gt[i] = stoks[tk[i]];
        }

        // ---- prologue: issue chunks 0..2 ----
        issue_chunk(0, smem, pu4, pv4, h4, stoks, tid); CP_COMMIT();
        issue_chunk(1, smem, pu4, pv4, h4, stoks, tid); CP_COMMIT();
        issue_chunk(2, smem, pu4, pv4, h4, stoks, tid); CP_COMMIT();

        // ================= phase A: chunks 0..15 =================
        u64 Ax[TPW], Az[TPW];
        #pragma unroll
        for (int i = 0; i < TPW; ++i) { Ax[i] = 0; Az[i] = 0; }

        #pragma unroll 1
        for (int t = 0; t < 16; ++t) {
            CP_WAIT2();
            __syncthreads();
            issue_chunk(t + 3, smem, pu4, pv4, h4, stoks, tid);
            CP_COMMIT();

            if (gvalid) {
                const float* ubl = smem + (t & 3) * STAGE_F + lane;
                const ulonglong2* hb = (const ulonglong2*)(smem + (t & 3) * STAGE_F + 2048);

                #pragma unroll 4
                for (int k4 = 0; k4 < 16; ++k4) {
                    const float* up = ubl + k4 * 128;
                    u64 u01 = pack2(up[0],  up[32]);
                    u64 u23 = pack2(up[64], up[96]);
                    #pragma unroll
                    for (int i = 0; i < TPW; ++i) {
                        ulonglong2 x = hb[tk[i] * 16 + k4];
                        Ax[i] = fma2(x.x, u01, Ax[i]);
                        Az[i] = fma2(x.y, u23, Az[i]);
                    }
                }
            }
        }

        // pack (iv,iv) into binter (per-warp private region)
        if (gvalid) {
            #pragma unroll
            for (int i = 0; i < TPW; ++i) {
                float f0, f1, f2, f3;
                unpack2(Ax[i], f0, f1);
                unpack2(Az[i], f2, f3);
                const float iv = (f0 + f1) + (f2 + f3);
                bint[tk[i] * 32 + lane] = pack2(iv, iv);
            }
        }
        __syncwarp();

        // ================= phase B: chunks 16..23 =================
        u64 S[TPW], Q[TPW];
        #pragma unroll
        for (int i = 0; i < TPW; ++i) { S[i] = 0; Q[i] = 0; }

        #pragma unroll 1
        for (int j = 0; j < 8; ++j) {
            const int t = 16 + j;
            if (j < 6)      { CP_WAIT2(); }
            else if (j == 6){ CP_WAIT1(); }
            else            { CP_WAIT0(); }
            __syncthreads();
            if (t + 3 < 24) {
                issue_chunk(t + 3, smem, pu4, pv4, h4, stoks, tid);
                CP_COMMIT();
            }

            if (gvalid) {
                const ulonglong2* vb = (const ulonglong2*)(smem + (t & 3) * STAGE_F);

                u64 Px[TPW], Pz[TPW];
                #pragma unroll
                for (int i = 0; i < TPW; ++i) { Px[i] = 0; Pz[i] = 0; }

                #pragma unroll 4
                for (int rb = 0; rb < 16; ++rb) {
                    ulonglong2 v0 = vb[(2 * rb)     * 32 + lane];
                    ulonglong2 v1 = vb[(2 * rb + 1) * 32 + lane];
                    #pragma unroll
                    for (int i = 0; i < TPW; ++i) {
                        ulonglong2 bb = ((const ulonglong2*)(bint + tk[i] * 32))[rb];
                        Px[i] = fma2(bb.x, v0.x, Px[i]);
                        Pz[i] = fma2(bb.x, v0.y, Pz[i]);
                        Px[i] = fma2(bb.y, v1.x, Px[i]);
                        Pz[i] = fma2(bb.y, v1.y, Pz[i]);
                    }
                }

                #pragma unroll
                for (int i = 0; i < TPW; ++i) {
                    if (!vd[i]) continue;
                    ulonglong2 hv = h2[(size_t)gt[i] * 256 + j * 32 + lane];
                    u64 dx = fma2(al2, Px[i], hv.x);
                    u64 dz = fma2(al2, Pz[i], hv.y);
                    S[i] = add2(S[i], add2(dx, dz));
                    Q[i] = fma2(dx, dx, Q[i]);
                    Q[i] = fma2(dz, dz, Q[i]);
                    ulonglong2 dd; dd.x = dx; dd.y = dz;
                    out2[(size_t)gt[i] * 256 + j * 32 + lane] = dd;
                }
            }
        }

        // ---- LN finalize + normalize ----
        if (gvalid) {
            float s[TPW], q[TPW];
            #pragma unroll
            for (int i = 0; i < TPW; ++i) {
                float lo, hi;
                unpack2(S[i], lo, hi); s[i] = lo + hi;
                unpack2(Q[i], lo, hi); q[i] = lo + hi;
            }
            #pragma unroll
            for (int o = 16; o > 0; o >>= 1) {
                #pragma unroll
                for (int i = 0; i < TPW; ++i) {
                    s[i] += __shfl_xor_sync(0xffffffffu, s[i], o);
                    q[i] += __shfl_xor_sync(0xffffffffu, q[i], o);
                }
            }
            const ulonglong2* g2 = (const ulonglong2*)gamma;
            const ulonglong2* b2 = (const ulonglong2*)beta;
            #pragma unroll
            for (int i = 0; i < TPW; ++i) {
                if (!vd[i]) continue;
                const float mn = s[i] * (1.0f / H_DIM);
                const float rs = rsqrtf(q[i] * (1.0f / H_DIM) - mn * mn + LN_EPS);
                const u64 nm2 = pack2(-mn, -mn);
                const u64 rs2 = pack2(rs, rs);
                ulonglong2* op = out2 + (size_t)gt[i] * 256 + lane;
                #pragma unroll
                for (int c = 0; c < 8; ++c) {
                    ulonglong2 d = op[c * 32];
                    ulonglong2 g = g2[c * 32 + lane];
                    ulonglong2 bb = b2[c * 32 + lane];
                    u64 tx = mul2(add2(d.x, nm2), rs2);
                    u64 tz = mul2(add2(d.y, nm2), rs2);
                    ulonglong2 o_;
                    o_.x = fma2(tx, g.x, bb.x);
                    o_.y = fma2(tz, g.y, bb.y);
                    op[c * 32] = o_;
                }
            }
        }
        __syncthreads();   // stoks / s_item / ring reuse safety
    }
}

extern "C" void kernel_launch(void* const* d_in, const int* in_sizes, int n_in,
                              void* d_out, int out_size)
{
    const float* h     = (const float*)d_in[0];
    const float* la    = (const float*)d_in[1];
    const float* gamma = (const float*)d_in[2];
    const float* beta  = (const float*)d_in[3];
    const float* pu    = (const float*)d_in[4];
    const float* pv    = (const float*)d_in[5];
    const int*   ids   = (const int*)d_in[6];
    float*       out   = (float*)d_out;

    build_all_kernel<<<BUILD_BLOCKS, NTH>>>(ids);

    cudaFuncSetAttribute(div_inject_kernel,
                         cudaFuncAttributeMaxDynamicSharedMemorySize, SMEM_BYTES);
    div_inject_kernel<<<GRID_MAIN, NTH, SMEM_BYTES>>>(h, la, gamma, beta, pu, pv, out);
}